// round 2
// baseline (speedup 1.0000x reference)
#include <cuda_runtime.h>
#include <math.h>

// Problem constants (fixed shapes)
#define BT   32768      // B*T
#define Dm   128
#define Hh   64
#define Kc   2048

#define TOK_PB   128    // tokens per block in argmin kernel
#define CODE_CH  32     // codes per smem chunk

// Output layout (float32, tuple flattened in order: out, ids, commitment, codebook)
#define OUT_IDS   (BT * Hh)            // 2097152
#define OUT_COMM  (OUT_IDS + BT)
#define OUT_CODE  (OUT_COMM + BT)

// Device scratch (no allocations allowed in kernel_launch)
__device__ float g_a[Kc];
__device__ float g_b[Kc];
__device__ int   g_ids[BT];

// --------------------------------------------------------------------------
// Packed f32x2 FMA (sm_103a; ptxas never emits FFMA2 from C++)
// --------------------------------------------------------------------------
__device__ __forceinline__ void ffma2(unsigned long long& d,
                                      unsigned long long a,
                                      unsigned long long b) {
    asm("fma.rn.f32x2 %0, %1, %2, %0;" : "+l"(d) : "l"(a), "l"(b));
}
__device__ __forceinline__ float lo32(unsigned long long v) {
    return __int_as_float((int)(unsigned)(v & 0xffffffffull));
}
__device__ __forceinline__ float hi32(unsigned long long v) {
    return __int_as_float((int)(unsigned)(v >> 32));
}

// --------------------------------------------------------------------------
// Kernel 1: per-code constants  a_k = 1/(2*sum exp(w_lv)),
//                               b_k = 0.5*sum(w_lv) + ||mu_e||^2 * a_k
// One warp per code. grid = Kc/8 blocks of 256 threads.
// --------------------------------------------------------------------------
__global__ __launch_bounds__(256) void precompute_kernel(const float* __restrict__ emb) {
    int k    = blockIdx.x * 8 + (threadIdx.x >> 5);
    int lane = threadIdx.x & 31;
    if (k >= Kc) return;
    const float* row = emb + (size_t)k * Dm;
    float2 mu = *(const float2*)(row + 2 * lane);
    float2 lv = *(const float2*)(row + Hh + 2 * lane);
    float e2 = mu.x * mu.x + mu.y * mu.y;
    float se = expf(lv.x) + expf(lv.y);
    float sl = lv.x + lv.y;
    #pragma unroll
    for (int o = 16; o; o >>= 1) {
        e2 += __shfl_xor_sync(0xffffffffu, e2, o);
        se += __shfl_xor_sync(0xffffffffu, se, o);
        sl += __shfl_xor_sync(0xffffffffu, sl, o);
    }
    if (lane == 0) {
        float a = 0.5f / se;
        g_a[k] = a;
        g_b[k] = 0.5f * sl + e2 * a;
    }
}

// --------------------------------------------------------------------------
// Kernel 2: argmin over codes.
// Block: 256 threads, 128 tokens. Threads: ty = tid>>3 (0..31), tx = tid&7.
// Thread handles tokens {ty + 32*i, i<4} x codes {tx + 8*j, j<4} per 32-code
// chunk. Dot accumulators packed as f32x2 over the K dimension (pairs k,k+1).
// --------------------------------------------------------------------------
__global__ __launch_bounds__(256) void argmin_kernel(const float* __restrict__ x,
                                                     const float* __restrict__ emb) {
    __shared__ float A_s[TOK_PB][68];     // token mu, padded rows (272B, 16B-aligned)
    __shared__ float B_s[CODE_CH][68];    // code  mu
    __shared__ float Ci_s[TOK_PB];
    __shared__ float a_s[CODE_CH], b_s[CODE_CH];

    int tid  = threadIdx.x;
    int warp = tid >> 5, lane = tid & 31;
    int tok0 = blockIdx.x * TOK_PB;

    // ---- Load token tile: mu -> A_s, C_i = ||mu||^2 + sum exp(logvar) ----
    #pragma unroll 4
    for (int i = 0; i < 16; i++) {
        int t = warp * 16 + i;
        float4 v = *(const float4*)(x + (size_t)(tok0 + t) * Dm + lane * 4);
        float p;
        if (lane < 16) {
            *(float4*)&A_s[t][lane * 4] = v;
            p = v.x * v.x + v.y * v.y + v.z * v.z + v.w * v.w;
        } else {
            p = expf(v.x) + expf(v.y) + expf(v.z) + expf(v.w);
        }
        #pragma unroll
        for (int o = 16; o; o >>= 1) p += __shfl_xor_sync(0xffffffffu, p, o);
        if (lane == 0) Ci_s[t] = p;
    }
    __syncthreads();

    int ty = tid >> 3, tx = tid & 7;
    float Ci[4];
    #pragma unroll
    for (int i = 0; i < 4; i++) Ci[i] = Ci_s[ty + 32 * i];

    float best[4];
    int   bidx[4];
    #pragma unroll
    for (int i = 0; i < 4; i++) { best[i] = 3.4e38f; bidx[i] = 0; }

    for (int ch = 0; ch < Kc / CODE_CH; ch++) {
        int c0 = ch * CODE_CH;
        __syncthreads();   // previous chunk's B_s reads done
        // load 32 codes x 64 floats (512 float4 / 256 threads = 2 each)
        #pragma unroll
        for (int u = 0; u < 2; u++) {
            int idx = tid + 256 * u;
            int c = idx >> 4, q = idx & 15;
            float4 v = *(const float4*)(emb + (size_t)(c0 + c) * Dm + q * 4);
            *(float4*)&B_s[c][q * 4] = v;
        }
        if (tid < CODE_CH) { a_s[tid] = g_a[c0 + tid]; b_s[tid] = g_b[c0 + tid]; }
        __syncthreads();

        unsigned long long acc[4][4];
        #pragma unroll
        for (int i = 0; i < 4; i++)
            #pragma unroll
            for (int j = 0; j < 4; j++) acc[i][j] = 0ull;

        #pragma unroll 8
        for (int k = 0; k < Hh; k += 4) {
            ulonglong2 av[4], bv[4];
            #pragma unroll
            for (int i = 0; i < 4; i++)
                av[i] = *(const ulonglong2*)&A_s[ty + 32 * i][k];
            #pragma unroll
            for (int j = 0; j < 4; j++)
                bv[j] = *(const ulonglong2*)&B_s[tx + 8 * j][k];
            #pragma unroll
            for (int i = 0; i < 4; i++)
                #pragma unroll
                for (int j = 0; j < 4; j++) {
                    ffma2(acc[i][j], av[i].x, bv[j].x);
                    ffma2(acc[i][j], av[i].y, bv[j].y);
                }
        }

        // fold scores into running argmin (codes ascending => strict < matches
        // jnp.argmin first-min tie-break)
        #pragma unroll
        for (int j = 0; j < 4; j++) {
            int   c  = c0 + tx + 8 * j;
            float aa = a_s[tx + 8 * j];
            float bb = b_s[tx + 8 * j];
            #pragma unroll
            for (int i = 0; i < 4; i++) {
                float dot = lo32(acc[i][j]) + hi32(acc[i][j]);
                float s = fmaf(aa, fmaf(-2.0f, dot, Ci[i]), bb);
                if (s < best[i]) { best[i] = s; bidx[i] = c; }
            }
        }
    }

    // reduce over the 8 tx-threads sharing each ty (consecutive lanes)
    #pragma unroll
    for (int i = 0; i < 4; i++) {
        float s = best[i];
        int   c = bidx[i];
        #pragma unroll
        for (int o = 1; o < 8; o <<= 1) {
            float s2 = __shfl_xor_sync(0xffffffffu, s, o);
            int   c2 = __shfl_xor_sync(0xffffffffu, c, o);
            if (s2 < s || (s2 == s && c2 < c)) { s = s2; c = c2; }
        }
        if (tx == 0) g_ids[tok0 + ty + 32 * i] = c;
    }
}

// --------------------------------------------------------------------------
// Kernel 3: epilogue. One warp per token (8 tokens / 256-thread block).
//   out[h]       = w[h] + exp(0.5*w[64+h]) * z[h]
//   commitment   = codebook = mean_d (w[d] - x[d])^2
//   ids as float
// --------------------------------------------------------------------------
__global__ __launch_bounds__(256) void epilogue_kernel(const float* __restrict__ x,
                                                       const float* __restrict__ emb,
                                                       const float* __restrict__ z,
                                                       float* __restrict__ out) {
    int warp = threadIdx.x >> 5, lane = threadIdx.x & 31;
    int token = blockIdx.x * 8 + warp;
    int id = g_ids[token];
    const float* w  = emb + (size_t)id * Dm;
    const float* xr = x + (size_t)token * Dm;

    float4 wv = *(const float4*)(w  + lane * 4);
    float4 xv = *(const float4*)(xr + lane * 4);
    float d0 = wv.x - xv.x, d1 = wv.y - xv.y, d2 = wv.z - xv.z, d3 = wv.w - xv.w;
    float p = d0 * d0 + d1 * d1 + d2 * d2 + d3 * d3;
    #pragma unroll
    for (int o = 16; o; o >>= 1) p += __shfl_xor_sync(0xffffffffu, p, o);

    #pragma unroll
    for (int r = 0; r < 2; r++) {
        int h = lane + 32 * r;
        float mu = w[h];
        float lv = w[Hh + h];
        float zz = z[(size_t)token * Hh + h];
        out[(size_t)token * Hh + h] = fmaf(expf(0.5f * lv), zz, mu);
    }
    if (lane == 0) {
        float m = p * (1.0f / (float)Dm);
        out[OUT_IDS  + token] = (float)id;
        out[OUT_COMM + token] = m;
        out[OUT_CODE + token] = m;
    }
}

// --------------------------------------------------------------------------
extern "C" void kernel_launch(void* const* d_in, const int* in_sizes, int n_in,
                              void* d_out, int out_size) {
    const float *x = nullptr, *emb = nullptr, *z = nullptr;
    for (int i = 0; i < n_in; i++) {
        if (in_sizes[i] == BT * Dm)      x   = (const float*)d_in[i];
        else if (in_sizes[i] == Kc * Dm) emb = (const float*)d_in[i];
        else if (in_sizes[i] == BT * Hh) z   = (const float*)d_in[i];
    }
    float* out = (float*)d_out;

    precompute_kernel<<<Kc / 8, 256>>>(emb);
    argmin_kernel<<<BT / TOK_PB, 256>>>(x, emb);
    epilogue_kernel<<<BT / 8, 256>>>(x, emb, z, out);
    (void)out_size;
}

// round 4
// speedup vs baseline: 1.1160x; 1.1160x over previous
#include <cuda_runtime.h>
#include <math.h>

// Problem constants (fixed shapes)
#define BT   32768      // B*T
#define Dm   128
#define Hh   64
#define Kc   2048

#define TOK_PB   128    // tokens per block in argmin kernel
#define CODE_CH  128    // codes per smem chunk
#define STRIDE   68     // smem row stride (floats): 272B, 16B-aligned for cp.async

#define N_CHUNKS (Kc / CODE_CH)   // 16

// Output layout (float32, tuple flattened in order: out, ids, commitment, codebook)
#define OUT_IDS   (BT * Hh)
#define OUT_COMM  (OUT_IDS + BT)
#define OUT_CODE  (OUT_COMM + BT)

typedef unsigned long long ull;

// Device scratch
__device__ __align__(16) float g_a[Kc];
__device__ __align__(16) float g_b[Kc];
__device__ int g_ids[BT];

// --------------------------------------------------------------------------
// Packed f32x2 FMA (sm_103a; ptxas never emits FFMA2 from C++)
// --------------------------------------------------------------------------
__device__ __forceinline__ void ffma2(ull& d, ull a, ull b) {
    asm("fma.rn.f32x2 %0, %1, %2, %0;" : "+l"(d) : "l"(a), "l"(b));
}
__device__ __forceinline__ float lo32(ull v) {
    return __int_as_float((int)(unsigned)(v & 0xffffffffull));
}
__device__ __forceinline__ float hi32(ull v) {
    return __int_as_float((int)(unsigned)(v >> 32));
}

// cp.async 16B (LDGSTS), L1-bypass
__device__ __forceinline__ void cp16(float* dst, const float* src) {
    unsigned d = (unsigned)__cvta_generic_to_shared(dst);
    asm volatile("cp.async.cg.shared.global [%0], [%1], 16;" :: "r"(d), "l"(src));
}
__device__ __forceinline__ void cp_commit() {
    asm volatile("cp.async.commit_group;");
}
__device__ __forceinline__ void cp_wait1() {
    asm volatile("cp.async.wait_group 1;" ::: "memory");
}

// --------------------------------------------------------------------------
// Kernel 1: per-code constants  a_k = 1/(2*sum exp(w_lv)),
//                               b_k = 0.5*sum(w_lv) + ||mu_e||^2 * a_k
// --------------------------------------------------------------------------
__global__ __launch_bounds__(256) void precompute_kernel(const float* __restrict__ emb) {
    int k    = blockIdx.x * 8 + (threadIdx.x >> 5);
    int lane = threadIdx.x & 31;
    if (k >= Kc) return;
    const float* row = emb + (size_t)k * Dm;
    float2 mu = *(const float2*)(row + 2 * lane);
    float2 lv = *(const float2*)(row + Hh + 2 * lane);
    float e2 = mu.x * mu.x + mu.y * mu.y;
    float se = expf(lv.x) + expf(lv.y);
    float sl = lv.x + lv.y;
    #pragma unroll
    for (int o = 16; o; o >>= 1) {
        e2 += __shfl_xor_sync(0xffffffffu, e2, o);
        se += __shfl_xor_sync(0xffffffffu, se, o);
        sl += __shfl_xor_sync(0xffffffffu, sl, o);
    }
    if (lane == 0) {
        float a = 0.5f / se;
        g_a[k] = a;
        g_b[k] = 0.5f * sl + e2 * a;
    }
}

// --------------------------------------------------------------------------
// Async prefetch of one 128-code chunk (mu rows) + a/b constants.
// 128 rows x 64 floats = 2048 16B units -> 8 per thread.
// --------------------------------------------------------------------------
__device__ __forceinline__ void prefetch_chunk(float* Bbuf, float* ABbuf,
                                               const float* __restrict__ emb,
                                               int c0, int tid) {
    #pragma unroll
    for (int u = 0; u < 8; u++) {
        int idx = tid + 256 * u;
        int row = idx >> 4, col = idx & 15;
        cp16(Bbuf + row * STRIDE + col * 4,
             emb + (size_t)(c0 + row) * Dm + col * 4);
    }
    if (tid < 32)       cp16(ABbuf + tid * 4,               g_a + c0 + tid * 4);
    else if (tid < 64)  cp16(ABbuf + 128 + (tid - 32) * 4,  g_b + c0 + (tid - 32) * 4);
}

// --------------------------------------------------------------------------
// Kernel 2: argmin over codes.
// Block: 256 threads = 16x16 (ty = tid>>4 tokens, tx = tid&15 codes).
// Per-thread tile: 8 tokens x 8 codes, f32x2-packed accumulators over k-pairs.
// Code tile (128 x 64) double-buffered via cp.async ping-pong.
// --------------------------------------------------------------------------
__global__ __launch_bounds__(256, 1) void argmin_kernel(const float* __restrict__ x,
                                                        const float* __restrict__ emb) {
    extern __shared__ float sm[];
    float* A_s  = sm;                              // 128*68
    float* B_s  = sm + TOK_PB * STRIDE;            // 2 x 128*68
    float* AB_s = B_s + 2 * CODE_CH * STRIDE;      // 2 x 256  (a[128] then b[128])
    float* Ci_s = AB_s + 512;                      // 128

    int tid  = threadIdx.x;
    int warp = tid >> 5, lane = tid & 31;
    int tok0 = blockIdx.x * TOK_PB;

    // Kick off chunk-0 prefetch immediately; overlap with A-tile load.
    prefetch_chunk(B_s, AB_s, emb, 0, tid);
    cp_commit();

    // ---- Load token tile: mu -> A_s, C_i = ||mu||^2 + sum exp(logvar) ----
    #pragma unroll 4
    for (int i = 0; i < 16; i++) {
        int t = warp * 16 + i;
        float4 v = *(const float4*)(x + (size_t)(tok0 + t) * Dm + lane * 4);
        float p;
        if (lane < 16) {
            *(float4*)&A_s[t * STRIDE + lane * 4] = v;
            p = v.x * v.x + v.y * v.y + v.z * v.z + v.w * v.w;
        } else {
            p = expf(v.x) + expf(v.y) + expf(v.z) + expf(v.w);
        }
        #pragma unroll
        for (int o = 16; o; o >>= 1) p += __shfl_xor_sync(0xffffffffu, p, o);
        if (lane == 0) Ci_s[t] = p;
    }

    int ty = tid >> 4, tx = tid & 15;
    const float* Arow = A_s + ty * STRIDE;

    float best[8];
    int   bidx[8];
    #pragma unroll
    for (int i = 0; i < 8; i++) { best[i] = 3.4e38f; bidx[i] = 0; }

    __syncthreads();   // A_s / Ci_s ready

    for (int ch = 0; ch < N_CHUNKS; ch++) {
        int buf = ch & 1;
        float* Bb  = B_s + buf * CODE_CH * STRIDE;
        float* ABb = AB_s + buf * 256;

        // Prefetch next chunk into the other buffer (safe: end-of-loop barrier
        // guarantees everyone finished reading it last iteration).
        if (ch < N_CHUNKS - 1)
            prefetch_chunk(B_s + (buf ^ 1) * CODE_CH * STRIDE,
                           AB_s + (buf ^ 1) * 256, emb, (ch + 1) * CODE_CH, tid);
        cp_commit();
        cp_wait1();        // chunk ch data landed (per-thread)
        __syncthreads();   // ... and visible to all threads

        ull acc[8][8];
        #pragma unroll
        for (int i = 0; i < 8; i++)
            #pragma unroll
            for (int j = 0; j < 8; j++) acc[i][j] = 0ull;

        const float* Brow = Bb + tx * STRIDE;

        #pragma unroll 2
        for (int k = 0; k < Hh; k += 2) {
            ull av[8], bv[8];
            #pragma unroll
            for (int i = 0; i < 8; i++)
                av[i] = *(const ull*)(Arow + i * 16 * STRIDE + k);
            #pragma unroll
            for (int j = 0; j < 8; j++)
                bv[j] = *(const ull*)(Brow + j * 16 * STRIDE + k);
            #pragma unroll
            for (int i = 0; i < 8; i++)
                #pragma unroll
                for (int j = 0; j < 8; j++)
                    ffma2(acc[i][j], av[i], bv[j]);
        }

        // Fold scores into running argmin (ascending code order + strict <
        // matches jnp.argmin first-min tie-break).
        int cbase = ch * CODE_CH + tx;
        #pragma unroll
        for (int j = 0; j < 8; j++) {
            float aa = ABb[tx + 16 * j];
            float bb = ABb[128 + tx + 16 * j];
            int   c  = cbase + 16 * j;
            #pragma unroll
            for (int i = 0; i < 8; i++) {
                float dot = lo32(acc[i][j]) + hi32(acc[i][j]);
                float s = fmaf(aa, fmaf(-2.0f, dot, Ci_s[ty + 16 * i]), bb);
                if (s < best[i]) { best[i] = s; bidx[i] = c; }
            }
        }
        __syncthreads();   // done reading Bb/ABb; next iter may overwrite
    }

    // Reduce over the 16 tx-threads per token (contiguous 16-lane groups).
    #pragma unroll
    for (int i = 0; i < 8; i++) {
        float s = best[i];
        int   c = bidx[i];
        #pragma unroll
        for (int o = 1; o < 16; o <<= 1) {
            float s2 = __shfl_xor_sync(0xffffffffu, s, o);
            int   c2 = __shfl_xor_sync(0xffffffffu, c, o);
            if (s2 < s || (s2 == s && c2 < c)) { s = s2; c = c2; }
        }
        if (tx == 0) g_ids[tok0 + ty + 16 * i] = c;
    }
}

// --------------------------------------------------------------------------
// Kernel 3: epilogue. One warp per token.
// --------------------------------------------------------------------------
__global__ __launch_bounds__(256) void epilogue_kernel(const float* __restrict__ x,
                                                       const float* __restrict__ emb,
                                                       const float* __restrict__ z,
                                                       float* __restrict__ out) {
    int warp = threadIdx.x >> 5, lane = threadIdx.x & 31;
    int token = blockIdx.x * 8 + warp;
    int id = g_ids[token];
    const float* w  = emb + (size_t)id * Dm;
    const float* xr = x + (size_t)token * Dm;

    float4 wv = *(const float4*)(w  + lane * 4);
    float4 xv = *(const float4*)(xr + lane * 4);
    float d0 = wv.x - xv.x, d1 = wv.y - xv.y, d2 = wv.z - xv.z, d3 = wv.w - xv.w;
    float p = d0 * d0 + d1 * d1 + d2 * d2 + d3 * d3;
    #pragma unroll
    for (int o = 16; o; o >>= 1) p += __shfl_xor_sync(0xffffffffu, p, o);

    #pragma unroll
    for (int r = 0; r < 2; r++) {
        int h = lane + 32 * r;
        float mu = w[h];
        float lv = w[Hh + h];
        float zz = z[(size_t)token * Hh + h];
        out[(size_t)token * Hh + h] = fmaf(expf(0.5f * lv), zz, mu);
    }
    if (lane == 0) {
        float m = p * (1.0f / (float)Dm);
        out[OUT_IDS  + token] = (float)id;
        out[OUT_COMM + token] = m;
        out[OUT_CODE + token] = m;
    }
}

// --------------------------------------------------------------------------
extern "C" void kernel_launch(void* const* d_in, const int* in_sizes, int n_in,
                              void* d_out, int out_size) {
    const float *x = nullptr, *emb = nullptr, *z = nullptr;
    for (int i = 0; i < n_in; i++) {
        if (in_sizes[i] == BT * Dm)      x   = (const float*)d_in[i];
        else if (in_sizes[i] == Kc * Dm) emb = (const float*)d_in[i];
        else if (in_sizes[i] == BT * Hh) z   = (const float*)d_in[i];
    }
    float* out = (float*)d_out;

    const int SMEM_BYTES = (TOK_PB * STRIDE + 2 * CODE_CH * STRIDE + 512 + 128) * 4;
    cudaFuncSetAttribute(argmin_kernel,
                         cudaFuncAttributeMaxDynamicSharedMemorySize, SMEM_BYTES);

    precompute_kernel<<<Kc / 8, 256>>>(emb);
    argmin_kernel<<<BT / TOK_PB, 256, SMEM_BYTES>>>(x, emb);
    epilogue_kernel<<<BT / 8, 256>>>(x, emb, z, out);
    (void)out_size;
}